// round 1
// baseline (speedup 1.0000x reference)
#include <cuda_runtime.h>
#include <cstdint>

// ---------------------------------------------------------------------------
// QuantumLayer: out[b,m] = e^{i*kappa*m^2} * sum_n G[m,n] * state[b,n]
// G built from scalars (gamma, phi, zeta) via Miatto&Quesada recurrences.
// Setup kernel (1 warp, fp64) builds G with Kerr folded in; main kernel is a
// batched 32x32 complex matvec using packed fp32x2 FMAs.
// ---------------------------------------------------------------------------

#define TPB 256

// Packed G: g_GG[m][p] = (gr[2p], gr[2p+1], gi[2p], gi[2p+1]) with kerr folded.
__device__ float4 g_GG[32][16];

struct dc { double re, im; };
__device__ __forceinline__ dc dmul(dc a, dc b){ return {a.re*b.re - a.im*b.im, a.re*b.im + a.im*b.re}; }
__device__ __forceinline__ dc dadd(dc a, dc b){ return {a.re + b.re, a.im + b.im}; }
__device__ __forceinline__ dc dscale(dc a, double s){ return {a.re*s, a.im*s}; }

__global__ void build_G(const float* __restrict__ gre, const float* __restrict__ gim,
                        const float* __restrict__ phip, const float* __restrict__ zre,
                        const float* __restrict__ zim, const float* __restrict__ kapp)
{
    const int m = threadIdx.x;  // 0..31, lane == Fock row index
    const double gr  = gre[0],  gi  = gim[0];
    const double phi = phip[0];
    const double zr  = zre[0],  zi  = zim[0];
    const double kap = kapp[0];

    const double r     = sqrt(zr*zr + zi*zi);
    const double delta = (r > 0.0) ? atan2(zi, zr) : 0.0;
    const double T     = tanh(r);
    const double sech  = 1.0 / cosh(r);

    const dc eidp  = { cos(delta + 2.0*phi), sin(delta + 2.0*phi) };
    const dc eiphi = { cos(phi), sin(phi) };
    const dc gamma = { gr,  gi };
    const dc gbar  = { gr, -gi };

    // g00 = exp(-0.5*(|gamma|^2 + conj(gamma)^2 * eidp * T)) * sqrt(sech)
    const dc gb2 = dmul(gbar, gbar);
    const dc t1  = dscale(dmul(gb2, eidp), T);
    const double zr_ = -0.5*(gr*gr + gi*gi + t1.re);
    const double zi_ = -0.5*t1.im;
    const double ez  = exp(zr_) * sqrt(sech);
    const dc g00 = { ez * cos(zi_), ez * sin(zi_) };

    const dc A = dadd(gamma, dscale(dmul(gbar, eidp), T));
    const dc B = dscale(eidp, T);
    const dc P = dscale(eiphi, sech);
    const dc Q = { cos(delta)*T, -sin(delta)*T };   // e^{-i delta} * T

    // --- column 0: serial recurrence (replicated per lane, lane keeps row m)
    dc c0 = g00;
    {
        dc gm1 = g00, gm2 = {0.0, 0.0};
        for (int k = 1; k < 32; k++) {
            dc ag = dmul(A, gm1);
            dc bg = dscale(dmul(B, gm2), sqrt((double)(k - 1)));
            dc g  = dscale({ag.re - bg.re, ag.im - bg.im}, 1.0 / sqrt((double)k));
            if (m == k) c0 = g;
            gm2 = gm1; gm1 = g;
        }
    }

    // Kerr phase for row m
    const double ang = kap * (double)(m * m);
    const dc kerr = { cos(ang), sin(ang) };
    const double sqm = sqrt((double)m);

    // write helper: store column n entry for row m (kerr folded)
    auto write_col = [&](int n, dc v) {
        dc w = dmul(kerr, v);
        float* p = reinterpret_cast<float*>(&g_GG[m][n >> 1]);
        p[(n & 1)]     = (float)w.re;
        p[2 + (n & 1)] = (float)w.im;
    };

    dc cur = c0, prev = {0.0, 0.0};
    write_col(0, cur);

    // --- remaining columns: parallel over m, shfl for the (m-1) term
    for (int n = 0; n < 31; n++) {
        double ur = __shfl_up_sync(0xffffffffu, cur.re, 1);
        double ui = __shfl_up_sync(0xffffffffu, cur.im, 1);
        if (m == 0) { ur = 0.0; ui = 0.0; }  // also killed by sqm=0
        // term = sqrt(m)*cur[m-1] - gbar*cur[m]
        dc gc = dmul(gbar, cur);
        dc term = { sqm*ur - gc.re, sqm*ui - gc.im };
        dc pt = dmul(P, term);
        dc qp = dscale(dmul(Q, prev), sqrt((double)n));
        dc next = dscale({pt.re + qp.re, pt.im + qp.im}, 1.0 / sqrt((double)(n + 1)));
        prev = cur; cur = next;
        write_col(n + 1, cur);
    }
}

__device__ __forceinline__ unsigned long long ffma2(unsigned long long a,
                                                    unsigned long long b,
                                                    unsigned long long c)
{
    unsigned long long d;
    asm("fma.rn.f32x2 %0, %1, %2, %3;" : "=l"(d) : "l"(a), "l"(b), "l"(c));
    return d;
}

__global__ void __launch_bounds__(TPB)
apply_k(const float* __restrict__ sre, const float* __restrict__ sim,
        float* __restrict__ out, int B)
{
    __shared__ float4 GG[32][16];
    {
        const float4* src = reinterpret_cast<const float4*>(g_GG);
        float4* dst = reinterpret_cast<float4*>(GG);
        for (int i = threadIdx.x; i < 32 * 16; i += TPB) dst[i] = src[i];
    }
    __syncthreads();

    const int b = blockIdx.x * TPB + threadIdx.x;
    if (b >= B) return;

    // Load this thread's state row (one 128B line each for re/im).
    union SU { float4 v[8]; unsigned long long q[16]; };
    SU R, I;
    const float4* rp = reinterpret_cast<const float4*>(sre + (size_t)b * 32);
    const float4* ip = reinterpret_cast<const float4*>(sim + (size_t)b * 32);
#pragma unroll
    for (int k = 0; k < 8; k++) { R.v[k] = rp[k]; I.v[k] = ip[k]; }

    float2* op = reinterpret_cast<float2*>(out + (size_t)b * 64);

#pragma unroll 4
    for (int m = 0; m < 32; m++) {
        unsigned long long a1 = 0ull, a2 = 0ull, a3 = 0ull, a4 = 0ull;
#pragma unroll
        for (int p = 0; p < 16; p++) {
            union G4 { float4 v; unsigned long long q[2]; } g;
            g.v = GG[m][p];
            a1 = ffma2(g.q[0], R.q[p], a1);  // gr * sr
            a2 = ffma2(g.q[1], I.q[p], a2);  // gi * si
            a3 = ffma2(g.q[1], R.q[p], a3);  // gi * sr
            a4 = ffma2(g.q[0], I.q[p], a4);  // gr * si
        }
        float2 A1 = *reinterpret_cast<float2*>(&a1);
        float2 A2 = *reinterpret_cast<float2*>(&a2);
        float2 A3 = *reinterpret_cast<float2*>(&a3);
        float2 A4 = *reinterpret_cast<float2*>(&a4);
        float ore = (A1.x + A1.y) - (A2.x + A2.y);
        float oim = (A3.x + A3.y) + (A4.x + A4.y);
        op[m] = make_float2(ore, oim);
    }
}

extern "C" void kernel_launch(void* const* d_in, const int* in_sizes, int n_in,
                              void* d_out, int out_size)
{
    const float* state_re = (const float*)d_in[0];
    const float* state_im = (const float*)d_in[1];
    const float* gamma_re = (const float*)d_in[2];
    const float* gamma_im = (const float*)d_in[3];
    const float* phi      = (const float*)d_in[4];
    const float* zeta_re  = (const float*)d_in[5];
    const float* zeta_im  = (const float*)d_in[6];
    const float* kappa    = (const float*)d_in[7];

    const int B = in_sizes[0] / 32;

    build_G<<<1, 32>>>(gamma_re, gamma_im, phi, zeta_re, zeta_im, kappa);

    const int blocks = (B + TPB - 1) / TPB;
    apply_k<<<blocks, TPB>>>(state_re, state_im, (float*)d_out, B);
}

// round 2
// speedup vs baseline: 1.3267x; 1.3267x over previous
#include <cuda_runtime.h>
#include <cstdint>

// ---------------------------------------------------------------------------
// QuantumLayer: out[b,m] = e^{i*kappa*m^2} * sum_n G[m,n] * state[b,n]
// build_G (1 warp, fp64) -> g_GG (global) -> memcpyAsync -> cGG (__constant__)
// apply_k: 2 states/thread, G via constant port (LDCU, uniform regs),
//          packed fp32x2 FMAs. No shared-memory broadcast traffic.
// ---------------------------------------------------------------------------

#define TPB 128

// Packed G: [m][p] = (gr[2p], gr[2p+1], gi[2p], gi[2p+1]) with kerr folded.
__device__   float4 g_GG[32][16];
__constant__ float4 cGG[32][16];

struct dc { double re, im; };
__device__ __forceinline__ dc dmul(dc a, dc b){ return {a.re*b.re - a.im*b.im, a.re*b.im + a.im*b.re}; }
__device__ __forceinline__ dc dadd(dc a, dc b){ return {a.re + b.re, a.im + b.im}; }
__device__ __forceinline__ dc dscale(dc a, double s){ return {a.re*s, a.im*s}; }

__global__ void build_G(const float* __restrict__ gre, const float* __restrict__ gim,
                        const float* __restrict__ phip, const float* __restrict__ zre,
                        const float* __restrict__ zim, const float* __restrict__ kapp)
{
    const int m = threadIdx.x;  // 0..31, lane == Fock row index
    const double gr  = gre[0],  gi  = gim[0];
    const double phi = phip[0];
    const double zr  = zre[0],  zi  = zim[0];
    const double kap = kapp[0];

    const double r     = sqrt(zr*zr + zi*zi);
    const double delta = (r > 0.0) ? atan2(zi, zr) : 0.0;
    const double T     = tanh(r);
    const double sech  = 1.0 / cosh(r);

    const dc eidp  = { cos(delta + 2.0*phi), sin(delta + 2.0*phi) };
    const dc eiphi = { cos(phi), sin(phi) };
    const dc gamma = { gr,  gi };
    const dc gbar  = { gr, -gi };

    // g00 = exp(-0.5*(|gamma|^2 + conj(gamma)^2 * eidp * T)) * sqrt(sech)
    const dc gb2 = dmul(gbar, gbar);
    const dc t1  = dscale(dmul(gb2, eidp), T);
    const double zr_ = -0.5*(gr*gr + gi*gi + t1.re);
    const double zi_ = -0.5*t1.im;
    const double ez  = exp(zr_) * sqrt(sech);
    const dc g00 = { ez * cos(zi_), ez * sin(zi_) };

    const dc A = dadd(gamma, dscale(dmul(gbar, eidp), T));
    const dc B = dscale(eidp, T);
    const dc P = dscale(eiphi, sech);
    const dc Q = { cos(delta)*T, -sin(delta)*T };   // e^{-i delta} * T

    // --- column 0: serial recurrence (replicated per lane, lane keeps row m)
    dc c0 = g00;
    {
        dc gm1 = g00, gm2 = {0.0, 0.0};
        for (int k = 1; k < 32; k++) {
            dc ag = dmul(A, gm1);
            dc bg = dscale(dmul(B, gm2), sqrt((double)(k - 1)));
            dc g  = dscale({ag.re - bg.re, ag.im - bg.im}, 1.0 / sqrt((double)k));
            if (m == k) c0 = g;
            gm2 = gm1; gm1 = g;
        }
    }

    // Kerr phase for row m
    const double ang = kap * (double)(m * m);
    const dc kerr = { cos(ang), sin(ang) };
    const double sqm = sqrt((double)m);

    auto write_col = [&](int n, dc v) {
        dc w = dmul(kerr, v);
        float* p = reinterpret_cast<float*>(&g_GG[m][n >> 1]);
        p[(n & 1)]     = (float)w.re;
        p[2 + (n & 1)] = (float)w.im;
    };

    dc cur = c0, prev = {0.0, 0.0};
    write_col(0, cur);

    for (int n = 0; n < 31; n++) {
        double ur = __shfl_up_sync(0xffffffffu, cur.re, 1);
        double ui = __shfl_up_sync(0xffffffffu, cur.im, 1);
        if (m == 0) { ur = 0.0; ui = 0.0; }
        dc gc = dmul(gbar, cur);
        dc term = { sqm*ur - gc.re, sqm*ui - gc.im };
        dc pt = dmul(P, term);
        dc qp = dscale(dmul(Q, prev), sqrt((double)n));
        dc next = dscale({pt.re + qp.re, pt.im + qp.im}, 1.0 / sqrt((double)(n + 1)));
        prev = cur; cur = next;
        write_col(n + 1, cur);
    }
}

__device__ __forceinline__ unsigned long long ffma2(unsigned long long a,
                                                    unsigned long long b,
                                                    unsigned long long c)
{
    unsigned long long d;
    asm("fma.rn.f32x2 %0, %1, %2, %3;" : "=l"(d) : "l"(a), "l"(b), "l"(c));
    return d;
}

union SU { float4 v[8]; unsigned long long q[16]; };
union G4 { float4 v; unsigned long long q[2]; };

__global__ void __launch_bounds__(TPB, 3)
apply_k(const float* __restrict__ sre, const float* __restrict__ sim,
        float* __restrict__ out, int B)
{
    const int b0 = blockIdx.x * (2 * TPB) + threadIdx.x;
    const int b1 = b0 + TPB;
    if (b0 >= B) return;
    const bool has1 = (b1 < B);

    // State rows: one 128B line each for re/im, per state.
    SU R0, I0, R1, I1;
    {
        const float4* rp0 = reinterpret_cast<const float4*>(sre + (size_t)b0 * 32);
        const float4* ip0 = reinterpret_cast<const float4*>(sim + (size_t)b0 * 32);
#pragma unroll
        for (int k = 0; k < 8; k++) { R0.v[k] = rp0[k]; I0.v[k] = ip0[k]; }
        if (has1) {
            const float4* rp1 = reinterpret_cast<const float4*>(sre + (size_t)b1 * 32);
            const float4* ip1 = reinterpret_cast<const float4*>(sim + (size_t)b1 * 32);
#pragma unroll
            for (int k = 0; k < 8; k++) { R1.v[k] = rp1[k]; I1.v[k] = ip1[k]; }
        } else {
#pragma unroll
            for (int k = 0; k < 8; k++) { R1.v[k] = make_float4(0,0,0,0); I1.v[k] = R1.v[k]; }
        }
    }

    float2* op0 = reinterpret_cast<float2*>(out + (size_t)b0 * 64);
    float2* op1 = reinterpret_cast<float2*>(out + (size_t)b1 * 64);

#pragma unroll 4
    for (int m = 0; m < 32; m++) {
        unsigned long long a1 = 0ull, a2 = 0ull, a3 = 0ull, a4 = 0ull;
        unsigned long long c1 = 0ull, c2 = 0ull, c3 = 0ull, c4 = 0ull;
#pragma unroll
        for (int p = 0; p < 16; p++) {
            G4 g; g.v = cGG[m][p];               // constant port: uniform LDCU
            a1 = ffma2(g.q[0], R0.q[p], a1);     // gr * sr
            a2 = ffma2(g.q[1], I0.q[p], a2);     // gi * si
            a3 = ffma2(g.q[1], R0.q[p], a3);     // gi * sr
            a4 = ffma2(g.q[0], I0.q[p], a4);     // gr * si
            c1 = ffma2(g.q[0], R1.q[p], c1);
            c2 = ffma2(g.q[1], I1.q[p], c2);
            c3 = ffma2(g.q[1], R1.q[p], c3);
            c4 = ffma2(g.q[0], I1.q[p], c4);
        }
        {
            float2 A1 = *reinterpret_cast<float2*>(&a1);
            float2 A2 = *reinterpret_cast<float2*>(&a2);
            float2 A3 = *reinterpret_cast<float2*>(&a3);
            float2 A4 = *reinterpret_cast<float2*>(&a4);
            op0[m] = make_float2((A1.x + A1.y) - (A2.x + A2.y),
                                 (A3.x + A3.y) + (A4.x + A4.y));
        }
        if (has1) {
            float2 C1 = *reinterpret_cast<float2*>(&c1);
            float2 C2 = *reinterpret_cast<float2*>(&c2);
            float2 C3 = *reinterpret_cast<float2*>(&c3);
            float2 C4 = *reinterpret_cast<float2*>(&c4);
            op1[m] = make_float2((C1.x + C1.y) - (C2.x + C2.y),
                                 (C3.x + C3.y) + (C4.x + C4.y));
        }
    }
}

extern "C" void kernel_launch(void* const* d_in, const int* in_sizes, int n_in,
                              void* d_out, int out_size)
{
    const float* state_re = (const float*)d_in[0];
    const float* state_im = (const float*)d_in[1];
    const float* gamma_re = (const float*)d_in[2];
    const float* gamma_im = (const float*)d_in[3];
    const float* phi      = (const float*)d_in[4];
    const float* zeta_re  = (const float*)d_in[5];
    const float* zeta_im  = (const float*)d_in[6];
    const float* kappa    = (const float*)d_in[7];

    const int B = in_sizes[0] / 32;

    build_G<<<1, 32>>>(gamma_re, gamma_im, phi, zeta_re, zeta_im, kappa);

    // Stage G into constant memory (D2D memcpy node — graph-capturable).
    void *csym = nullptr, *gsym = nullptr;
    cudaGetSymbolAddress(&csym, cGG);
    cudaGetSymbolAddress(&gsym, g_GG);
    cudaMemcpyAsync(csym, gsym, sizeof(float4) * 32 * 16,
                    cudaMemcpyDeviceToDevice, 0);

    const int blocks = (B + 2 * TPB - 1) / (2 * TPB);
    apply_k<<<blocks, TPB>>>(state_re, state_im, (float*)d_out, B);
}

// round 3
// speedup vs baseline: 1.8306x; 1.3798x over previous
#include <cuda_runtime.h>
#include <cuda_bf16.h>
#include <cstdint>

// ---------------------------------------------------------------------------
// QuantumLayer: out[b,m] = e^{i*kappa*m^2} * sum_n G[m,n] * state[b,n]
//
// Reformulated as real GEMM: out[B,64] = X[B,64] @ W[64,64]
//   X[b, 0:32]  = state_re row,  X[b, 32:64] = state_im row
//   W[n,   2m] = Gr'(m,n)   W[n,   2m+1] = Gi'(m,n)     (G' = kerr * G)
//   W[32+n,2m] = -Gi'(m,n)  W[32+n,2m+1] = Gr'(m,n)
// so out column 2m = Re(out_m), 2m+1 = Im(out_m)  -> directly matches the
// [B, 32, 2] float32 output layout.
//
// Executed with bf16 mma.sync.m16n8k16 using hi/lo split of BOTH operands:
//   D = Xh*Wh + Xl*Wh + Xh*Wl      (drop Xl*Wl ~ 2^-18)
// ---------------------------------------------------------------------------

__device__ __nv_bfloat16 g_Wh[64 * 64];   // W^T stored as [j][k] hi part
__device__ __nv_bfloat16 g_Wl[64 * 64];   // lo part

// ======================== build W (1 warp, fp64) ===========================
struct dc { double re, im; };
__device__ __forceinline__ dc dmul(dc a, dc b){ return {a.re*b.re - a.im*b.im, a.re*b.im + a.im*b.re}; }
__device__ __forceinline__ dc dadd(dc a, dc b){ return {a.re + b.re, a.im + b.im}; }
__device__ __forceinline__ dc dscale(dc a, double s){ return {a.re*s, a.im*s}; }

__global__ void build_G(const float* __restrict__ gre, const float* __restrict__ gim,
                        const float* __restrict__ phip, const float* __restrict__ zre,
                        const float* __restrict__ zim, const float* __restrict__ kapp)
{
    const int m = threadIdx.x;  // 0..31, lane == Fock row index
    const double gr  = gre[0],  gi  = gim[0];
    const double phi = phip[0];
    const double zr  = zre[0],  zi  = zim[0];
    const double kap = kapp[0];

    // per-lane sqrt tables, shared via shfl (kills serial sqrt/div chains)
    const double sq_m  = sqrt((double)m);
    const double rsq_m = (m > 0) ? 1.0 / sq_m : 0.0;
    auto SQ  = [&](int k){ return __shfl_sync(0xffffffffu, sq_m,  k); };
    auto RSQ = [&](int k){ return __shfl_sync(0xffffffffu, rsq_m, k); };

    const double r2 = zr*zr + zi*zi;
    const double r  = sqrt(r2);
    dc eid;                                   // e^{i delta} = zeta/|zeta|
    if (r > 0.0) { eid = { zr / r, zi / r }; } else { eid = { 1.0, 0.0 }; }

    const double er  = exp(r);
    const double ei  = 1.0 / er;
    const double ch  = 0.5 * (er + ei);
    const double T   = (0.5 * (er - ei)) / ch; // tanh r
    const double sech= 1.0 / ch;

    double sph, cph; sincos(phi, &sph, &cph);
    const dc eiphi  = { cph, sph };
    const dc e2iphi = dmul(eiphi, eiphi);
    const dc eidp   = dmul(eid, e2iphi);      // e^{i(delta + 2 phi)}

    const dc gamma = { gr,  gi };
    const dc gbar  = { gr, -gi };

    // g00 = exp(-0.5*(|gamma|^2 + conj(gamma)^2 * eidp * T)) * sqrt(sech)
    const dc gb2 = dmul(gbar, gbar);
    const dc t1  = dscale(dmul(gb2, eidp), T);
    const double zr_ = -0.5*(gr*gr + gi*gi + t1.re);
    const double zi_ = -0.5*t1.im;
    double s0, c0p; sincos(zi_, &s0, &c0p);
    const double ez  = exp(zr_) * sqrt(sech);
    const dc g00 = { ez * c0p, ez * s0 };

    const dc A = dadd(gamma, dscale(dmul(gbar, eidp), T));
    const dc B = dscale(eidp, T);
    const dc P = dscale(eiphi, sech);
    const dc Q = { eid.re * T, -eid.im * T };  // e^{-i delta} tanh r

    // --- column 0: serial recurrence (replicated per lane, lane keeps row m)
    dc c0 = g00;
    {
        dc gm1 = g00, gm2 = {0.0, 0.0};
        for (int k = 1; k < 32; k++) {
            dc ag = dmul(A, gm1);
            dc bg = dscale(dmul(B, gm2), SQ(k - 1));
            dc g  = dscale({ag.re - bg.re, ag.im - bg.im}, RSQ(k));
            if (m == k) c0 = g;
            gm2 = gm1; gm1 = g;
        }
    }

    // Kerr phase for row m
    double sk, ck; sincos(kap * (double)(m * m), &sk, &ck);
    const dc kerr = { ck, sk };

    auto put = [&](int j, int k, float x){
        __nv_bfloat16 h = __float2bfloat16(x);
        float l = x - __bfloat162float(h);
        g_Wh[j * 64 + k] = h;
        g_Wl[j * 64 + k] = __float2bfloat16(l);
    };
    auto write_col = [&](int n, dc v){
        dc w = dmul(kerr, v);
        float wr = (float)w.re, wi = (float)w.im;
        put(2*m,     n,      wr);
        put(2*m + 1, n,      wi);
        put(2*m,     32 + n, -wi);
        put(2*m + 1, 32 + n, wr);
    };

    dc cur = c0, prev = {0.0, 0.0};
    write_col(0, cur);

    // --- remaining columns: parallel over m, shfl for the (m-1) term
    for (int n = 0; n < 31; n++) {
        double ur = __shfl_up_sync(0xffffffffu, cur.re, 1);
        double ui = __shfl_up_sync(0xffffffffu, cur.im, 1);
        if (m == 0) { ur = 0.0; ui = 0.0; }
        dc gc = dmul(gbar, cur);
        dc term = { sq_m * ur - gc.re, sq_m * ui - gc.im };
        dc pt = dmul(P, term);
        dc qp = dscale(dmul(Q, prev), SQ(n));
        dc next = dscale({pt.re + qp.re, pt.im + qp.im}, RSQ(n + 1));
        prev = cur; cur = next;
        write_col(n + 1, cur);
    }
}

// ============================ apply (tensor) ===============================

__device__ __forceinline__ void split2(float2 v, uint32_t& h, uint32_t& l)
{
    uint32_t hh;
    asm("cvt.rn.bf16x2.f32 %0, %1, %2;" : "=r"(hh) : "f"(v.y), "f"(v.x)); // hi=v.y, lo=v.x
    float hx = __uint_as_float(hh << 16);
    float hy = __uint_as_float(hh & 0xffff0000u);
    float lx = v.x - hx;
    float ly = v.y - hy;
    uint32_t ll;
    asm("cvt.rn.bf16x2.f32 %0, %1, %2;" : "=r"(ll) : "f"(ly), "f"(lx));
    h = hh; l = ll;
}

__device__ __forceinline__ void mma_bf16(float& c0, float& c1, float& c2, float& c3,
                                         uint32_t a0, uint32_t a1, uint32_t a2, uint32_t a3,
                                         uint32_t b0, uint32_t b1)
{
    asm("mma.sync.aligned.m16n8k16.row.col.f32.bf16.bf16.f32 "
        "{%0,%1,%2,%3}, {%4,%5,%6,%7}, {%8,%9}, {%0,%1,%2,%3};"
        : "+f"(c0), "+f"(c1), "+f"(c2), "+f"(c3)
        : "r"(a0), "r"(a1), "r"(a2), "r"(a3), "r"(b0), "r"(b1));
}

#define WSTR 72   // smem row stride in bf16 (bank = 4g+tid -> conflict-free)

__global__ void __launch_bounds__(256)
apply_k(const float* __restrict__ sre, const float* __restrict__ sim,
        float* __restrict__ out, int B)
{
    __shared__ __nv_bfloat16 sWh[64 * WSTR];
    __shared__ __nv_bfloat16 sWl[64 * WSTR];
    for (int idx = threadIdx.x; idx < 64 * 64; idx += 256) {
        int j = idx >> 6, k = idx & 63;
        sWh[j * WSTR + k] = g_Wh[idx];
        sWl[j * WSTR + k] = g_Wl[idx];
    }
    __syncthreads();

    const int warp = threadIdx.x >> 5;
    const int lane = threadIdx.x & 31;
    const int g    = lane >> 2;     // 0..7
    const int tid  = lane & 3;      // 0..3

    const int bbase = blockIdx.x * 128 + warp * 16;   // 16 batch rows per warp
    const int r0 = bbase + g;
    const int r1 = r0 + 8;
    const int r0c = (r0 < B) ? r0 : (B - 1);
    const int r1c = (r1 < B) ? r1 : (B - 1);

    // A fragments: Ah/Al[kt][reg]  (reg 0,2 from row r0; 1,3 from row r1)
    uint32_t Ah[4][4], Al[4][4];
    {
        const float2* pr = reinterpret_cast<const float2*>(sre + (size_t)r0c * 32);
        const float2* pi = reinterpret_cast<const float2*>(sim + (size_t)r0c * 32);
        split2(pr[tid],      Ah[0][0], Al[0][0]);
        split2(pr[tid +  4], Ah[0][2], Al[0][2]);
        split2(pr[tid +  8], Ah[1][0], Al[1][0]);
        split2(pr[tid + 12], Ah[1][2], Al[1][2]);
        split2(pi[tid],      Ah[2][0], Al[2][0]);
        split2(pi[tid +  4], Ah[2][2], Al[2][2]);
        split2(pi[tid +  8], Ah[3][0], Al[3][0]);
        split2(pi[tid + 12], Ah[3][2], Al[3][2]);
    }
    {
        const float2* pr = reinterpret_cast<const float2*>(sre + (size_t)r1c * 32);
        const float2* pi = reinterpret_cast<const float2*>(sim + (size_t)r1c * 32);
        split2(pr[tid],      Ah[0][1], Al[0][1]);
        split2(pr[tid +  4], Ah[0][3], Al[0][3]);
        split2(pr[tid +  8], Ah[1][1], Al[1][1]);
        split2(pr[tid + 12], Ah[1][3], Al[1][3]);
        split2(pi[tid],      Ah[2][1], Al[2][1]);
        split2(pi[tid +  4], Ah[2][3], Al[2][3]);
        split2(pi[tid +  8], Ah[3][1], Al[3][1]);
        split2(pi[tid + 12], Ah[3][3], Al[3][3]);
    }

#pragma unroll
    for (int nt = 0; nt < 8; nt++) {
        float c0 = 0.f, c1 = 0.f, c2 = 0.f, c3 = 0.f;
        const int j = nt * 8 + g;
        const __nv_bfloat16* bh = &sWh[j * WSTR + 2 * tid];
        const __nv_bfloat16* bl = &sWl[j * WSTR + 2 * tid];
#pragma unroll
        for (int kt = 0; kt < 4; kt++) {
            uint32_t b0h = *reinterpret_cast<const uint32_t*>(bh + kt * 16);
            uint32_t b1h = *reinterpret_cast<const uint32_t*>(bh + kt * 16 + 8);
            uint32_t b0l = *reinterpret_cast<const uint32_t*>(bl + kt * 16);
            uint32_t b1l = *reinterpret_cast<const uint32_t*>(bl + kt * 16 + 8);
            mma_bf16(c0, c1, c2, c3, Ah[kt][0], Ah[kt][1], Ah[kt][2], Ah[kt][3], b0h, b1h);
            mma_bf16(c0, c1, c2, c3, Al[kt][0], Al[kt][1], Al[kt][2], Al[kt][3], b0h, b1h);
            mma_bf16(c0, c1, c2, c3, Ah[kt][0], Ah[kt][1], Ah[kt][2], Ah[kt][3], b0l, b1l);
        }
        const int jc = nt * 8 + 2 * tid;
        if (r0 < B)
            *reinterpret_cast<float2*>(out + (size_t)r0 * 64 + jc) = make_float2(c0, c1);
        if (r1 < B)
            *reinterpret_cast<float2*>(out + (size_t)r1 * 64 + jc) = make_float2(c2, c3);
    }
}

extern "C" void kernel_launch(void* const* d_in, const int* in_sizes, int n_in,
                              void* d_out, int out_size)
{
    const float* state_re = (const float*)d_in[0];
    const float* state_im = (const float*)d_in[1];
    const float* gamma_re = (const float*)d_in[2];
    const float* gamma_im = (const float*)d_in[3];
    const float* phi      = (const float*)d_in[4];
    const float* zeta_re  = (const float*)d_in[5];
    const float* zeta_im  = (const float*)d_in[6];
    const float* kappa    = (const float*)d_in[7];

    const int B = in_sizes[0] / 32;

    build_G<<<1, 32>>>(gamma_re, gamma_im, phi, zeta_re, zeta_im, kappa);

    const int blocks = (B + 127) / 128;   // 128 states per CTA (8 warps x 16)
    apply_k<<<blocks, 256>>>(state_re, state_im, (float*)d_out, B);
}

// round 4
// speedup vs baseline: 2.6843x; 1.4663x over previous
#include <cuda_runtime.h>
#include <cuda_bf16.h>
#include <cstdint>

// ---------------------------------------------------------------------------
// QuantumLayer: out[b,m] = e^{i*kappa*m^2} * sum_n G[m,n] * state[b,n]
// GEMM form: out[B,64] = X[B,64] @ W[64,64], X=[re|im],
//   cols 2m/2m+1 = Re/Im (with Kerr folded into W).
// bf16 mma.m16n8k16, hi/lo split: D = Xh*Wh + Xl*Wh + Xh*Wl.
//
// Layout tricks (all pre-baked into W by build_G):
//  - K permuted per 16-chunk so A fragments load as one float4 per thread.
//  - W stored fragment-native: uint4 {b0h,b1h,b0l,b1l} per (j, kt, t).
//  - N permuted so tile-pair accumulators store as float4 (STG.128).
//  - 2 batch tiles (32 states) per warp: B fragments reused from registers.
// ---------------------------------------------------------------------------

#define TPB 256

// [js][ 4*kt + t ] uint4, row stride 17 (16 + 1 pad) to dodge bank aliasing.
__device__ uint4 g_Wf[64 * 17];

// ======================== build W (1 warp, fp64) ===========================
struct dc { double re, im; };
__device__ __forceinline__ dc dmul(dc a, dc b){ return {a.re*b.re - a.im*b.im, a.re*b.im + a.im*b.re}; }
__device__ __forceinline__ dc dadd(dc a, dc b){ return {a.re + b.re, a.im + b.im}; }
__device__ __forceinline__ dc dscale(dc a, double s){ return {a.re*s, a.im*s}; }

__global__ void build_G(const float* __restrict__ gre, const float* __restrict__ gim,
                        const float* __restrict__ phip, const float* __restrict__ zre,
                        const float* __restrict__ zim, const float* __restrict__ kapp)
{
    const int m = threadIdx.x;  // 0..31, lane == Fock row index
    const double gr  = gre[0],  gi  = gim[0];
    const double phi = phip[0];
    const double zr  = zre[0],  zi  = zim[0];
    const double kap = kapp[0];

    const double sq_m  = sqrt((double)m);
    const double rsq_m = (m > 0) ? 1.0 / sq_m : 0.0;
    auto SQ  = [&](int k){ return __shfl_sync(0xffffffffu, sq_m,  k); };
    auto RSQ = [&](int k){ return __shfl_sync(0xffffffffu, rsq_m, k); };

    const double r2 = zr*zr + zi*zi;
    const double r  = sqrt(r2);
    dc eid;                                   // e^{i delta} = zeta/|zeta|
    if (r > 0.0) { eid = { zr / r, zi / r }; } else { eid = { 1.0, 0.0 }; }

    const double er  = exp(r);
    const double ei  = 1.0 / er;
    const double ch  = 0.5 * (er + ei);
    const double T   = (0.5 * (er - ei)) / ch; // tanh r
    const double sech= 1.0 / ch;

    double sph, cph; sincos(phi, &sph, &cph);
    const dc eiphi  = { cph, sph };
    const dc e2iphi = dmul(eiphi, eiphi);
    const dc eidp   = dmul(eid, e2iphi);      // e^{i(delta + 2 phi)}

    const dc gamma = { gr,  gi };
    const dc gbar  = { gr, -gi };

    const dc gb2 = dmul(gbar, gbar);
    const dc t1  = dscale(dmul(gb2, eidp), T);
    const double zr_ = -0.5*(gr*gr + gi*gi + t1.re);
    const double zi_ = -0.5*t1.im;
    double s0, c0p; sincos(zi_, &s0, &c0p);
    const double ez  = exp(zr_) * sqrt(sech);
    const dc g00 = { ez * c0p, ez * s0 };

    const dc A = dadd(gamma, dscale(dmul(gbar, eidp), T));
    const dc B = dscale(eidp, T);
    const dc P = dscale(eiphi, sech);
    const dc Q = { eid.re * T, -eid.im * T };  // e^{-i delta} tanh r

    // --- column 0: serial recurrence (replicated per lane, lane keeps row m)
    dc c0 = g00;
    {
        dc gm1 = g00, gm2 = {0.0, 0.0};
        for (int k = 1; k < 32; k++) {
            dc ag = dmul(A, gm1);
            dc bg = dscale(dmul(B, gm2), SQ(k - 1));
            dc g  = dscale({ag.re - bg.re, ag.im - bg.im}, RSQ(k));
            if (m == k) c0 = g;
            gm2 = gm1; gm1 = g;
        }
    }

    double sk, ck; sincos(kap * (double)(m * m), &sk, &ck);
    const dc kerr = { ck, sk };

    // Write W^T[j_gmem][k] into the permuted fragment-native layout.
    auto put = [&](int j_gmem, int k, float x){
        __nv_bfloat16 h = __float2bfloat16(x);
        float l = x - __bfloat162float(h);
        // N-permutation: gmem col -> (nt, pos) -> storage row js
        int u  = j_gmem >> 4, rem = j_gmem & 15;
        int tt = rem >> 2,    w4  = rem & 3;
        int nt = 2*u + (w4 >> 1);
        int p  = 2*tt + (w4 & 1);
        int js = nt*8 + p;
        // K location: chunk c, thread t, quad q (data order; pi handled by layout)
        int c = k >> 4, t = (k >> 2) & 3, q = k & 3;
        __nv_bfloat16* base = reinterpret_cast<__nv_bfloat16*>(&g_Wf[js*17 + c*4 + t]);
        base[q]     = h;                       // words x,y = b0h,b1h
        base[4 + q] = __float2bfloat16(l);     // words z,w = b0l,b1l
    };
    auto write_col = [&](int n, dc v){
        dc w = dmul(kerr, v);
        float wr = (float)w.re, wi = (float)w.im;
        put(2*m,     n,      wr);
        put(2*m + 1, n,      wi);
        put(2*m,     32 + n, -wi);
        put(2*m + 1, 32 + n, wr);
    };

    dc cur = c0, prev = {0.0, 0.0};
    write_col(0, cur);

    for (int n = 0; n < 31; n++) {
        double ur = __shfl_up_sync(0xffffffffu, cur.re, 1);
        double ui = __shfl_up_sync(0xffffffffu, cur.im, 1);
        if (m == 0) { ur = 0.0; ui = 0.0; }
        dc gc = dmul(gbar, cur);
        dc term = { sq_m * ur - gc.re, sq_m * ui - gc.im };
        dc pt = dmul(P, term);
        dc qp = dscale(dmul(Q, prev), SQ(n));
        dc next = dscale({pt.re + qp.re, pt.im + qp.im}, RSQ(n + 1));
        prev = cur; cur = next;
        write_col(n + 1, cur);
    }
}

// ============================ apply (tensor) ===============================

__device__ __forceinline__ void split2(float x, float y, uint32_t& h, uint32_t& l)
{
    uint32_t hh;
    asm("cvt.rn.bf16x2.f32 %0, %1, %2;" : "=r"(hh) : "f"(y), "f"(x)); // lo=x, hi=y
    float hx = __uint_as_float(hh << 16);
    float hy = __uint_as_float(hh & 0xffff0000u);
    float lx = x - hx;
    float ly = y - hy;
    uint32_t ll;
    asm("cvt.rn.bf16x2.f32 %0, %1, %2;" : "=r"(ll) : "f"(ly), "f"(lx));
    h = hh; l = ll;
}

__device__ __forceinline__ void mma_bf16(float* c,
                                         uint32_t a0, uint32_t a1, uint32_t a2, uint32_t a3,
                                         uint32_t b0, uint32_t b1)
{
    asm("mma.sync.aligned.m16n8k16.row.col.f32.bf16.bf16.f32 "
        "{%0,%1,%2,%3}, {%4,%5,%6,%7}, {%8,%9}, {%0,%1,%2,%3};"
        : "+f"(c[0]), "+f"(c[1]), "+f"(c[2]), "+f"(c[3])
        : "r"(a0), "r"(a1), "r"(a2), "r"(a3), "r"(b0), "r"(b1));
}

__global__ void __launch_bounds__(TPB, 2)
apply_k(const float* __restrict__ sre, const float* __restrict__ sim,
        float* __restrict__ out, int B)
{
    __shared__ uint4 sW[64 * 17];
    for (int i = threadIdx.x; i < 64 * 17; i += TPB) sW[i] = g_Wf[i];
    __syncthreads();

    const int warp = threadIdx.x >> 5;
    const int lane = threadIdx.x & 31;
    const int g    = lane >> 2;     // 0..7
    const int t    = lane & 3;      // 0..3

    const int wbase = blockIdx.x * 256 + warp * 32;   // 32 states per warp

    int row0[2], row1[2];
#pragma unroll
    for (int tile = 0; tile < 2; tile++) {
        row0[tile] = wbase + tile * 16 + g;
        row1[tile] = row0[tile] + 8;
    }

    // ---- front-batched A loads: 16x LDG.128 ----
    float4 L[16];
#pragma unroll
    for (int tile = 0; tile < 2; tile++) {
        int rc0 = (row0[tile] < B) ? row0[tile] : (B - 1);
        int rc1 = (row1[tile] < B) ? row1[tile] : (B - 1);
        const float4* pr0 = reinterpret_cast<const float4*>(sre + (size_t)rc0 * 32);
        const float4* pi0 = reinterpret_cast<const float4*>(sim + (size_t)rc0 * 32);
        const float4* pr1 = reinterpret_cast<const float4*>(sre + (size_t)rc1 * 32);
        const float4* pi1 = reinterpret_cast<const float4*>(sim + (size_t)rc1 * 32);
        L[tile * 8 + 0] = pr0[t];
        L[tile * 8 + 1] = pr0[t + 4];
        L[tile * 8 + 2] = pi0[t];
        L[tile * 8 + 3] = pi0[t + 4];
        L[tile * 8 + 4] = pr1[t];
        L[tile * 8 + 5] = pr1[t + 4];
        L[tile * 8 + 6] = pi1[t];
        L[tile * 8 + 7] = pi1[t + 4];
    }

    // A fragments: [tile][kt][reg] reg: 0=a0(row0 lo) 1=a1(row1 lo) 2=a2(row0 hi) 3=a3(row1 hi)
    uint32_t Ah[2][4][4], Al[2][4][4];
#pragma unroll
    for (int tile = 0; tile < 2; tile++) {
#pragma unroll
        for (int kt = 0; kt < 4; kt++) {
            float4 v0 = L[tile * 8 + kt];       // row0: kt0=re lo16, kt1=re hi16, kt2=im lo, kt3=im hi
            float4 v1 = L[tile * 8 + 4 + kt];   // row1
            split2(v0.x, v0.y, Ah[tile][kt][0], Al[tile][kt][0]);
            split2(v0.z, v0.w, Ah[tile][kt][2], Al[tile][kt][2]);
            split2(v1.x, v1.y, Ah[tile][kt][1], Al[tile][kt][1]);
            split2(v1.z, v1.w, Ah[tile][kt][3], Al[tile][kt][3]);
        }
    }

#pragma unroll
    for (int u = 0; u < 4; u++) {
        float acc[2][2][4];                 // [ntHalf][tile][frag]
#pragma unroll
        for (int a = 0; a < 2; a++)
#pragma unroll
            for (int b = 0; b < 2; b++)
#pragma unroll
                for (int c = 0; c < 4; c++) acc[a][b][c] = 0.f;

#pragma unroll
        for (int h2 = 0; h2 < 2; h2++) {
            const int nt = 2 * u + h2;
            const uint4* bp = &sW[(nt * 8 + g) * 17 + t];
#pragma unroll
            for (int kt = 0; kt < 4; kt++) {
                uint4 b = bp[kt * 4];       // {b0h, b1h, b0l, b1l}
#pragma unroll
                for (int tile = 0; tile < 2; tile++) {
                    mma_bf16(acc[h2][tile], Ah[tile][kt][0], Ah[tile][kt][1],
                                            Ah[tile][kt][2], Ah[tile][kt][3], b.x, b.y);
                    mma_bf16(acc[h2][tile], Al[tile][kt][0], Al[tile][kt][1],
                                            Al[tile][kt][2], Al[tile][kt][3], b.x, b.y);
                    mma_bf16(acc[h2][tile], Ah[tile][kt][0], Ah[tile][kt][1],
                                            Ah[tile][kt][2], Ah[tile][kt][3], b.z, b.w);
                }
            }
        }

        // stores: gmem cols 16u + 4t .. +3 (STG.128), rows row0/row1 per tile
        const int colb = 16 * u + 4 * t;
#pragma unroll
        for (int tile = 0; tile < 2; tile++) {
            if (row0[tile] < B) {
                float4 v = make_float4(acc[0][tile][0], acc[0][tile][1],
                                       acc[1][tile][0], acc[1][tile][1]);
                *reinterpret_cast<float4*>(out + (size_t)row0[tile] * 64 + colb) = v;
            }
            if (row1[tile] < B) {
                float4 v = make_float4(acc[0][tile][2], acc[0][tile][3],
                                       acc[1][tile][2], acc[1][tile][3]);
                *reinterpret_cast<float4*>(out + (size_t)row1[tile] * 64 + colb) = v;
            }
        }
    }
}

extern "C" void kernel_launch(void* const* d_in, const int* in_sizes, int n_in,
                              void* d_out, int out_size)
{
    const float* state_re = (const float*)d_in[0];
    const float* state_im = (const float*)d_in[1];
    const float* gamma_re = (const float*)d_in[2];
    const float* gamma_im = (const float*)d_in[3];
    const float* phi      = (const float*)d_in[4];
    const float* zeta_re  = (const float*)d_in[5];
    const float* zeta_im  = (const float*)d_in[6];
    const float* kappa    = (const float*)d_in[7];

    const int B = in_sizes[0] / 32;

    build_G<<<1, 32>>>(gamma_re, gamma_im, phi, zeta_re, zeta_im, kappa);

    const int blocks = (B + 255) / 256;   // 256 states per CTA (8 warps x 32)
    apply_k<<<blocks, TPB>>>(state_re, state_im, (float*)d_out, B);
}